// round 1
// baseline (speedup 1.0000x reference)
#include <cuda_runtime.h>
#include <math.h>

// Problem constants
#define BATCH  4
#define SEQ    2048
#define DMODEL 512
#define NHEADS 8
#define DHEAD  64
#define DFF    2048
#define NBLOCKS 6
#define NROWS  (BATCH * SEQ)   // 8192

// ---------------------------------------------------------------------------
// Scratch (device globals: allocation-free rule)
// ---------------------------------------------------------------------------
__device__ float g_h  [NROWS * DMODEL];
__device__ float g_y  [NROWS * DMODEL];
__device__ float g_a  [NROWS * DMODEL];
__device__ float g_ao [NROWS * DMODEL];
__device__ float g_q  [BATCH * NHEADS * SEQ * DHEAD];
__device__ float g_k  [BATCH * NHEADS * SEQ * DHEAD];
__device__ float g_v  [BATCH * NHEADS * SEQ * DHEAD];
__device__ float g_mid[NROWS * DFF];

__device__ __forceinline__ float gelu_exact(float x) {
    return 0.5f * x * (1.0f + erff(x * 0.70710678118654752f));
}

// ---------------------------------------------------------------------------
// Embedding + sinusoidal PE:  h[b,t,:] = embed[x[b,t],:] + pe[t,:]
// ---------------------------------------------------------------------------
__global__ void embed_k(const int* __restrict__ x, const float* __restrict__ E,
                        const float* __restrict__ pe, float* __restrict__ H) {
    int idx = blockIdx.x * blockDim.x + threadIdx.x;        // over 8192*128 float4s
    int row = idx >> 7;
    int c   = (idx & 127) << 2;
    int t   = row & (SEQ - 1);
    int tok = x[row];
    float4 e = *(const float4*)(E  + (size_t)tok * DMODEL + c);
    float4 p = *(const float4*)(pe + (size_t)t   * DMODEL + c);
    float4 o = make_float4(e.x + p.x, e.y + p.y, e.z + p.z, e.w + p.w);
    *(float4*)(H + (size_t)row * DMODEL + c) = o;
}

// ---------------------------------------------------------------------------
// SGEMM: C[M,N] = A[M,K] @ B[K,N] (+bias) (+gelu).  128x128x8 tiles, 256 thr,
// 8x8 per thread.  All dims are multiples of tile sizes -> no bounds checks.
// EPI: 0=plain, 1=+bias, 2=+bias+gelu
// ---------------------------------------------------------------------------
template <int EPI>
__global__ void __launch_bounds__(256) sgemm_k(
    const float* __restrict__ A, const float* __restrict__ B,
    const float* __restrict__ bias, float* __restrict__ C,
    int M, int N, int K)
{
    __shared__ float As[8][128];
    __shared__ float Bs[8][128];
    const int tid  = threadIdx.x;
    const int m0   = blockIdx.y * 128;
    const int n0   = blockIdx.x * 128;
    const int arow = tid >> 1;
    const int acol = (tid & 1) << 2;
    const int brow = tid >> 5;
    const int bcol = (tid & 31) << 2;
    const int ty   = tid >> 4;
    const int tx   = tid & 15;

    const float* Ap = A + (size_t)(m0 + arow) * K + acol;
    const float* Bp = B + (size_t)brow * N + n0 + bcol;

    float acc[8][8];
#pragma unroll
    for (int i = 0; i < 8; i++)
#pragma unroll
        for (int j = 0; j < 8; j++) acc[i][j] = 0.0f;

    for (int k0 = 0; k0 < K; k0 += 8) {
        float4 av = *(const float4*)(Ap + k0);
        float4 bv = *(const float4*)(Bp + (size_t)k0 * N);
        As[acol + 0][arow] = av.x;
        As[acol + 1][arow] = av.y;
        As[acol + 2][arow] = av.z;
        As[acol + 3][arow] = av.w;
        *(float4*)(&Bs[brow][bcol]) = bv;
        __syncthreads();
#pragma unroll
        for (int kk = 0; kk < 8; kk++) {
            float a[8], bn[8];
            *(float4*)&a[0]  = *(const float4*)&As[kk][ty * 8];
            *(float4*)&a[4]  = *(const float4*)&As[kk][ty * 8 + 4];
            *(float4*)&bn[0] = *(const float4*)&Bs[kk][tx * 8];
            *(float4*)&bn[4] = *(const float4*)&Bs[kk][tx * 8 + 4];
#pragma unroll
            for (int i = 0; i < 8; i++)
#pragma unroll
                for (int j = 0; j < 8; j++)
                    acc[i][j] = fmaf(a[i], bn[j], acc[i][j]);
        }
        __syncthreads();
    }

#pragma unroll
    for (int i = 0; i < 8; i++) {
        int row = m0 + ty * 8 + i;
        float* Crow = C + (size_t)row * N + n0 + tx * 8;
#pragma unroll
        for (int j = 0; j < 8; j += 4) {
            float4 v = make_float4(acc[i][j], acc[i][j+1], acc[i][j+2], acc[i][j+3]);
            if (EPI >= 1) {
                float4 bb = *(const float4*)(bias + n0 + tx * 8 + j);
                v.x += bb.x; v.y += bb.y; v.z += bb.z; v.w += bb.w;
            }
            if (EPI == 2) {
                v.x = gelu_exact(v.x); v.y = gelu_exact(v.y);
                v.z = gelu_exact(v.z); v.w = gelu_exact(v.w);
            }
            *(float4*)(Crow + j) = v;
        }
    }
}

// ---------------------------------------------------------------------------
// QKV SGEMM: same mainloop, epilogue scatters column n = d*24 + kv*8 + h of
// qkv into contiguous Q/K/V buffers laid out [B, H, T, DHEAD].
// M=8192, N=1536, K=512 fixed.
// ---------------------------------------------------------------------------
__global__ void __launch_bounds__(256) sgemm_qkv_k(
    const float* __restrict__ A, const float* __restrict__ B,
    float* __restrict__ Qo, float* __restrict__ Ko, float* __restrict__ Vo)
{
    const int K = DMODEL, N = 3 * DMODEL;
    __shared__ float As[8][128];
    __shared__ float Bs[8][128];
    const int tid  = threadIdx.x;
    const int m0   = blockIdx.y * 128;
    const int n0   = blockIdx.x * 128;
    const int arow = tid >> 1;
    const int acol = (tid & 1) << 2;
    const int brow = tid >> 5;
    const int bcol = (tid & 31) << 2;
    const int ty   = tid >> 4;
    const int tx   = tid & 15;

    const float* Ap = A + (size_t)(m0 + arow) * K + acol;
    const float* Bp = B + (size_t)brow * N + n0 + bcol;

    float acc[8][8];
#pragma unroll
    for (int i = 0; i < 8; i++)
#pragma unroll
        for (int j = 0; j < 8; j++) acc[i][j] = 0.0f;

    for (int k0 = 0; k0 < K; k0 += 8) {
        float4 av = *(const float4*)(Ap + k0);
        float4 bv = *(const float4*)(Bp + (size_t)k0 * N);
        As[acol + 0][arow] = av.x;
        As[acol + 1][arow] = av.y;
        As[acol + 2][arow] = av.z;
        As[acol + 3][arow] = av.w;
        *(float4*)(&Bs[brow][bcol]) = bv;
        __syncthreads();
#pragma unroll
        for (int kk = 0; kk < 8; kk++) {
            float a[8], bn[8];
            *(float4*)&a[0]  = *(const float4*)&As[kk][ty * 8];
            *(float4*)&a[4]  = *(const float4*)&As[kk][ty * 8 + 4];
            *(float4*)&bn[0] = *(const float4*)&Bs[kk][tx * 8];
            *(float4*)&bn[4] = *(const float4*)&Bs[kk][tx * 8 + 4];
#pragma unroll
            for (int i = 0; i < 8; i++)
#pragma unroll
                for (int j = 0; j < 8; j++)
                    acc[i][j] = fmaf(a[i], bn[j], acc[i][j]);
        }
        __syncthreads();
    }

#pragma unroll
    for (int i = 0; i < 8; i++) {
        int row = m0 + ty * 8 + i;
        int bidx = row >> 11;          // / SEQ
        int t    = row & (SEQ - 1);
#pragma unroll
        for (int j = 0; j < 8; j++) {
            int col = n0 + tx * 8 + j;
            int d   = col / 24;
            int r   = col - d * 24;
            int kv  = r >> 3;
            int hh  = r & 7;
            float* dst = (kv == 0) ? Qo : (kv == 1) ? Ko : Vo;
            dst[(((size_t)bidx * NHEADS + hh) * SEQ + t) * DHEAD + d] = acc[i][j];
        }
    }
}

// ---------------------------------------------------------------------------
// Flash attention (non-causal, full softmax).  One CTA per (64-query tile, h, b).
// Q/K stored d-major (transposed) in smem for the S GEMM; V and P j-major.
// Row stride 68 floats to bound transpose-store bank conflicts.
// ---------------------------------------------------------------------------
#define FLASH_LD 68
#define FLASH_SMEM (4 * 64 * FLASH_LD * 4)

__global__ void __launch_bounds__(256) flash_k(
    const float* __restrict__ Q, const float* __restrict__ Kg,
    const float* __restrict__ V, float* __restrict__ O)
{
    extern __shared__ float sm[];
    float* Qs = sm;                       // [d][i], stride 68
    float* Ks = sm + 64 * FLASH_LD;       // [d][j]
    float* Vs = sm + 2 * 64 * FLASH_LD;   // [j][d]
    float* Ps = sm + 3 * 64 * FLASH_LD;   // [j][i]

    const int tid = threadIdx.x;
    const int qt  = blockIdx.x;
    const int h   = blockIdx.y;
    const int b   = blockIdx.z;
    const int t0  = qt * 64;
    const size_t bh = ((size_t)b * NHEADS + h) * SEQ;

    const float* qbase = Q + (bh + t0) * DHEAD;
    for (int e = tid; e < 1024; e += 256) {
        int i  = e >> 4;
        int d4 = (e & 15) << 2;
        float4 qv = *(const float4*)(qbase + i * DHEAD + d4);
        Qs[(d4 + 0) * FLASH_LD + i] = qv.x;
        Qs[(d4 + 1) * FLASH_LD + i] = qv.y;
        Qs[(d4 + 2) * FLASH_LD + i] = qv.z;
        Qs[(d4 + 3) * FLASH_LD + i] = qv.w;
    }

    const int tr = tid >> 4;
    const int tc = tid & 15;

    float o[4][4];
    float mrow[4], lrow[4];
#pragma unroll
    for (int r = 0; r < 4; r++) {
        mrow[r] = -1e30f; lrow[r] = 0.0f;
#pragma unroll
        for (int c = 0; c < 4; c++) o[r][c] = 0.0f;
    }

    for (int j0 = 0; j0 < SEQ; j0 += 64) {
        __syncthreads();   // protect Ks/Vs/Ps from previous iteration's readers
        const float* kbase = Kg + (bh + j0) * DHEAD;
        const float* vbase = V  + (bh + j0) * DHEAD;
        for (int e = tid; e < 1024; e += 256) {
            int j  = e >> 4;
            int d4 = (e & 15) << 2;
            float4 kv = *(const float4*)(kbase + j * DHEAD + d4);
            Ks[(d4 + 0) * FLASH_LD + j] = kv.x;
            Ks[(d4 + 1) * FLASH_LD + j] = kv.y;
            Ks[(d4 + 2) * FLASH_LD + j] = kv.z;
            Ks[(d4 + 3) * FLASH_LD + j] = kv.w;
            float4 vv = *(const float4*)(vbase + j * DHEAD + d4);
            *(float4*)(Vs + j * FLASH_LD + d4) = vv;
        }
        __syncthreads();

        // S = Q @ K^T  (4x4 per thread)
        float s[4][4] = {};
#pragma unroll 8
        for (int kk = 0; kk < 64; kk++) {
            float4 q4 = *(const float4*)(Qs + kk * FLASH_LD + tr * 4);
            float4 k4 = *(const float4*)(Ks + kk * FLASH_LD + tc * 4);
            float qa[4] = {q4.x, q4.y, q4.z, q4.w};
            float ka[4] = {k4.x, k4.y, k4.z, k4.w};
#pragma unroll
            for (int r = 0; r < 4; r++)
#pragma unroll
                for (int c = 0; c < 4; c++)
                    s[r][c] = fmaf(qa[r], ka[c], s[r][c]);
        }

        // online softmax (row groups = 16 lanes sharing tr)
#pragma unroll
        for (int r = 0; r < 4; r++) {
            float rm = -1e30f;
#pragma unroll
            for (int c = 0; c < 4; c++) { s[r][c] *= 0.125f; rm = fmaxf(rm, s[r][c]); }
            rm = fmaxf(rm, __shfl_xor_sync(0xffffffffu, rm, 1));
            rm = fmaxf(rm, __shfl_xor_sync(0xffffffffu, rm, 2));
            rm = fmaxf(rm, __shfl_xor_sync(0xffffffffu, rm, 4));
            rm = fmaxf(rm, __shfl_xor_sync(0xffffffffu, rm, 8));
            float mnew = fmaxf(mrow[r], rm);
            float corr = __expf(mrow[r] - mnew);
            mrow[r] = mnew;
            float rs = 0.0f;
#pragma unroll
            for (int c = 0; c < 4; c++) {
                float pv = __expf(s[r][c] - mnew);
                s[r][c] = pv;
                rs += pv;
            }
            rs += __shfl_xor_sync(0xffffffffu, rs, 1);
            rs += __shfl_xor_sync(0xffffffffu, rs, 2);
            rs += __shfl_xor_sync(0xffffffffu, rs, 4);
            rs += __shfl_xor_sync(0xffffffffu, rs, 8);
            lrow[r] = lrow[r] * corr + rs;
#pragma unroll
            for (int c = 0; c < 4; c++) o[r][c] *= corr;
        }

        // store P transposed: Ps[j][i]
#pragma unroll
        for (int c = 0; c < 4; c++) {
            float4 pv = make_float4(s[0][c], s[1][c], s[2][c], s[3][c]);
            *(float4*)(Ps + (tc * 4 + c) * FLASH_LD + tr * 4) = pv;
        }
        __syncthreads();

        // O += P @ V
#pragma unroll 8
        for (int jj = 0; jj < 64; jj++) {
            float4 p4 = *(const float4*)(Ps + jj * FLASH_LD + tr * 4);
            float4 v4 = *(const float4*)(Vs + jj * FLASH_LD + tc * 4);
            float pa[4] = {p4.x, p4.y, p4.z, p4.w};
            float va[4] = {v4.x, v4.y, v4.z, v4.w};
#pragma unroll
            for (int r = 0; r < 4; r++)
#pragma unroll
                for (int c = 0; c < 4; c++)
                    o[r][c] = fmaf(pa[r], va[c], o[r][c]);
        }
    }

    // write out[b, t, h*64+d]
#pragma unroll
    for (int r = 0; r < 4; r++) {
        float inv = 1.0f / lrow[r];
        float4 ov = make_float4(o[r][0]*inv, o[r][1]*inv, o[r][2]*inv, o[r][3]*inv);
        *(float4*)(O + ((size_t)b * SEQ + t0 + tr * 4 + r) * DMODEL + h * DHEAD + tc * 4) = ov;
    }
}

// ---------------------------------------------------------------------------
// out = LayerNorm(a + resid) * g + bias.  One block (128 threads) per row.
// ---------------------------------------------------------------------------
__global__ void __launch_bounds__(128) add_ln_k(
    const float* __restrict__ A, const float* __restrict__ R,
    const float* __restrict__ g, const float* __restrict__ bb,
    float* __restrict__ out)
{
    __shared__ float red[4];
    int row = blockIdx.x;
    int tid = threadIdx.x;
    int warp = tid >> 5, lane = tid & 31;

    float4 a4 = *(const float4*)(A + (size_t)row * DMODEL + tid * 4);
    float4 r4 = *(const float4*)(R + (size_t)row * DMODEL + tid * 4);
    float x0 = a4.x + r4.x, x1 = a4.y + r4.y, x2 = a4.z + r4.z, x3 = a4.w + r4.w;

    float s = x0 + x1 + x2 + x3;
    s += __shfl_xor_sync(0xffffffffu, s, 16);
    s += __shfl_xor_sync(0xffffffffu, s, 8);
    s += __shfl_xor_sync(0xffffffffu, s, 4);
    s += __shfl_xor_sync(0xffffffffu, s, 2);
    s += __shfl_xor_sync(0xffffffffu, s, 1);
    if (lane == 0) red[warp] = s;
    __syncthreads();
    float mu = (red[0] + red[1] + red[2] + red[3]) * (1.0f / DMODEL);
    __syncthreads();

    float d0 = x0 - mu, d1 = x1 - mu, d2 = x2 - mu, d3 = x3 - mu;
    float s2 = d0*d0 + d1*d1 + d2*d2 + d3*d3;
    s2 += __shfl_xor_sync(0xffffffffu, s2, 16);
    s2 += __shfl_xor_sync(0xffffffffu, s2, 8);
    s2 += __shfl_xor_sync(0xffffffffu, s2, 4);
    s2 += __shfl_xor_sync(0xffffffffu, s2, 2);
    s2 += __shfl_xor_sync(0xffffffffu, s2, 1);
    if (lane == 0) red[warp] = s2;
    __syncthreads();
    float var = (red[0] + red[1] + red[2] + red[3]) * (1.0f / DMODEL);
    float rstd = rsqrtf(var + 1e-5f);

    float4 gv = *(const float4*)(g  + tid * 4);
    float4 bv = *(const float4*)(bb + tid * 4);
    float4 ov = make_float4(d0 * rstd * gv.x + bv.x,
                            d1 * rstd * gv.y + bv.y,
                            d2 * rstd * gv.z + bv.z,
                            d3 * rstd * gv.w + bv.w);
    *(float4*)(out + (size_t)row * DMODEL + tid * 4) = ov;
}

// ---------------------------------------------------------------------------
// Head: out[row] = dot(h[row,:], Whead[:,0]) + bhead.  One warp per row.
// ---------------------------------------------------------------------------
__global__ void head_k(const float* __restrict__ H, const float* __restrict__ W,
                       const float* __restrict__ bh, float* __restrict__ out)
{
    int gw   = (blockIdx.x * blockDim.x + threadIdx.x) >> 5;
    int lane = threadIdx.x & 31;
    const float* r = H + (size_t)gw * DMODEL;
    float s = 0.0f;
#pragma unroll
    for (int k = 0; k < DMODEL / 32; k++)
        s = fmaf(r[lane + k * 32], W[lane + k * 32], s);
    s += __shfl_xor_sync(0xffffffffu, s, 16);
    s += __shfl_xor_sync(0xffffffffu, s, 8);
    s += __shfl_xor_sync(0xffffffffu, s, 4);
    s += __shfl_xor_sync(0xffffffffu, s, 2);
    s += __shfl_xor_sync(0xffffffffu, s, 1);
    if (lane == 0) out[gw] = s + bh[0];
}

// ---------------------------------------------------------------------------
// Launcher
// ---------------------------------------------------------------------------
extern "C" void kernel_launch(void* const* d_in, const int* in_sizes, int n_in,
                              void* d_out, int out_size)
{
    const int*   x     = (const int*)  d_in[0];
    const float* embed = (const float*)d_in[1];
    const float* pe    = (const float*)d_in[2];
    const float* Wqkv  = (const float*)d_in[3];
    const float* W0    = (const float*)d_in[4];
    const float* g1    = (const float*)d_in[5];
    const float* b1    = (const float*)d_in[6];
    const float* g2    = (const float*)d_in[7];
    const float* b2    = (const float*)d_in[8];
    const float* Wl1   = (const float*)d_in[9];
    const float* bl1   = (const float*)d_in[10];
    const float* Wl2   = (const float*)d_in[11];
    const float* bl2   = (const float*)d_in[12];
    const float* Wh    = (const float*)d_in[13];
    const float* bh    = (const float*)d_in[14];
    float* out = (float*)d_out;

    float *hb, *yb, *ab, *aob, *qb, *kb, *vb, *midb;
    cudaGetSymbolAddress((void**)&hb,   g_h);
    cudaGetSymbolAddress((void**)&yb,   g_y);
    cudaGetSymbolAddress((void**)&ab,   g_a);
    cudaGetSymbolAddress((void**)&aob,  g_ao);
    cudaGetSymbolAddress((void**)&qb,   g_q);
    cudaGetSymbolAddress((void**)&kb,   g_k);
    cudaGetSymbolAddress((void**)&vb,   g_v);
    cudaGetSymbolAddress((void**)&midb, g_mid);

    cudaFuncSetAttribute(flash_k, cudaFuncAttributeMaxDynamicSharedMemorySize,
                         FLASH_SMEM);

    embed_k<<<(NROWS * (DMODEL / 4)) / 256, 256>>>(x, embed, pe, hb);

    for (int i = 0; i < NBLOCKS; i++) {
        sgemm_qkv_k<<<dim3(12, 64), 256>>>(
            hb, Wqkv + (size_t)i * DMODEL * 3 * DMODEL, qb, kb, vb);

        flash_k<<<dim3(SEQ / 64, NHEADS, BATCH), 256, FLASH_SMEM>>>(qb, kb, vb, aob);

        sgemm_k<0><<<dim3(4, 64), 256>>>(
            aob, W0 + (size_t)i * DMODEL * DMODEL, nullptr, ab,
            NROWS, DMODEL, DMODEL);

        add_ln_k<<<NROWS, 128>>>(ab, hb, g1 + i * DMODEL, b1 + i * DMODEL, yb);

        sgemm_k<2><<<dim3(16, 64), 256>>>(
            yb, Wl1 + (size_t)i * DMODEL * DFF, bl1 + i * DFF, midb,
            NROWS, DFF, DMODEL);

        sgemm_k<1><<<dim3(4, 64), 256>>>(
            midb, Wl2 + (size_t)i * DFF * DMODEL, bl2 + i * DMODEL, ab,
            NROWS, DMODEL, DFF);

        add_ln_k<<<NROWS, 128>>>(ab, yb, g2 + i * DMODEL, b2 + i * DMODEL, hb);
    }

    head_k<<<NROWS / 8, 256>>>(hb, Wh, bh, out);
}

// round 3
// speedup vs baseline: 1.4983x; 1.4983x over previous
#include <cuda_runtime.h>
#include <cuda_bf16.h>
#include <cstdint>
#include <math.h>

// Problem constants
#define BATCH  4
#define SEQ    2048
#define DMODEL 512
#define NHEADS 8
#define DHEAD  64
#define DFF    2048
#define NBLOCKS 6
#define NROWS  (BATCH * SEQ)   // 8192

// ---------------------------------------------------------------------------
// Scratch (device globals: allocation-free rule)
// ---------------------------------------------------------------------------
__device__ float g_h  [NROWS * DMODEL];
__device__ float g_y  [NROWS * DMODEL];
__device__ float g_a  [NROWS * DMODEL];
__device__ float g_ao [NROWS * DMODEL];
__device__ float g_q  [BATCH * NHEADS * SEQ * DHEAD];
__device__ float g_k  [BATCH * NHEADS * SEQ * DHEAD];
__device__ float g_v  [BATCH * NHEADS * SEQ * DHEAD];
__device__ float g_mid[NROWS * DFF];
// Transposed weights, [N][K] K-major
__device__ float g_wt_qkv[NBLOCKS * 3 * DMODEL * DMODEL];   // [6][1536][512] (n' = kv*512+h*64+d)
__device__ float g_wt_w0 [NBLOCKS * DMODEL * DMODEL];       // [6][512][512]
__device__ float g_wt_l1 [NBLOCKS * DFF * DMODEL];          // [6][2048][512]
__device__ float g_wt_l2 [NBLOCKS * DMODEL * DFF];          // [6][512][2048]

__device__ __forceinline__ float gelu_exact(float x) {
    return 0.5f * x * (1.0f + erff(x * 0.70710678118654752f));
}

// ---------------------------------------------------------------------------
// bf16 split helpers: x = hi + lo (each bf16), |x - hi - lo| <~ 2^-18 |x|
// ---------------------------------------------------------------------------
__device__ __forceinline__ void split2(float x, float y, uint32_t& hi, uint32_t& lo) {
    __nv_bfloat16 hx = __float2bfloat16_rn(x);
    __nv_bfloat16 hy = __float2bfloat16_rn(y);
    float rx = x - __bfloat162float(hx);
    float ry = y - __bfloat162float(hy);
    __nv_bfloat162 H; H.x = hx; H.y = hy;
    __nv_bfloat162 L = __floats2bfloat162_rn(rx, ry);
    hi = *reinterpret_cast<uint32_t*>(&H);
    lo = *reinterpret_cast<uint32_t*>(&L);
}

// m16n8k16 bf16 MMA, fp32 accum
__device__ __forceinline__ void mma_bf16(float* c, const uint32_t* a, const uint32_t* b) {
    asm volatile(
        "mma.sync.aligned.m16n8k16.row.col.f32.bf16.bf16.f32 "
        "{%0,%1,%2,%3}, {%4,%5,%6,%7}, {%8,%9}, {%0,%1,%2,%3};"
        : "+f"(c[0]), "+f"(c[1]), "+f"(c[2]), "+f"(c[3])
        : "r"(a[0]), "r"(a[1]), "r"(a[2]), "r"(a[3]), "r"(b[0]), "r"(b[1]));
}

// ---------------------------------------------------------------------------
// Embedding + sinusoidal PE
// ---------------------------------------------------------------------------
__global__ void embed_k(const int* __restrict__ x, const float* __restrict__ E,
                        const float* __restrict__ pe, float* __restrict__ H) {
    int idx = blockIdx.x * blockDim.x + threadIdx.x;
    int row = idx >> 7;
    int c   = (idx & 127) << 2;
    int t   = row & (SEQ - 1);
    int tok = x[row];
    float4 e = *(const float4*)(E  + (size_t)tok * DMODEL + c);
    float4 p = *(const float4*)(pe + (size_t)t   * DMODEL + c);
    *(float4*)(H + (size_t)row * DMODEL + c) =
        make_float4(e.x + p.x, e.y + p.y, e.z + p.z, e.w + p.w);
}

// ---------------------------------------------------------------------------
// Weight transposes:  W[K][N] row-major -> Wt[N][K] K-major
// ---------------------------------------------------------------------------
__global__ void wtrans_k(const float* __restrict__ W, float* __restrict__ Wt,
                         int K, int N) {
    __shared__ float t[32][33];
    int n0 = blockIdx.x * 32, k0 = blockIdx.y * 32;
    const float* Wz = W  + (size_t)blockIdx.z * K * N;
    float*      Wtz = Wt + (size_t)blockIdx.z * K * N;
    int tx = threadIdx.x, ty = threadIdx.y;       // 32 x 8
#pragma unroll
    for (int i = 0; i < 32; i += 8)
        t[ty + i][tx] = Wz[(size_t)(k0 + ty + i) * N + n0 + tx];
    __syncthreads();
#pragma unroll
    for (int i = 0; i < 32; i += 8)
        Wtz[(size_t)(n0 + ty + i) * K + k0 + tx] = t[tx][ty + i];
}

// QKV transpose + column permutation: Wt row n' = kv*512 + h*64 + d,
// original col n = d*24 + kv*8 + h.
__global__ void wqkvtrans_k(const float* __restrict__ W, float* __restrict__ Wt) {
    int z   = blockIdx.y;
    int idx = blockIdx.x * 256 + threadIdx.x;    // over 1536*512
    int k   = idx & 511;
    int np  = idx >> 9;
    int kv  = np >> 9, h = (np >> 6) & 7, d = np & 63;
    int n   = d * 24 + kv * 8 + h;
    Wt[(size_t)z * 1536 * 512 + idx] = W[((size_t)z * 512 + k) * 1536 + n];
}

// ---------------------------------------------------------------------------
// bf16x3 warp-MMA GEMM:  C[M,N] = A[M,K] @ Wt[N,K]^T
// CTA 128x128, 8 warps (64x32 each), K-chunk 32, 2 smem stages, 1 sync/chunk.
// smem per stage (b32 units): Ahi[128*20] Alo[128*20] Bhi[128*20] Blo[128*20]
// row stride 20 b32 (16 data + 4 pad) -> all fragment LDS are conflict-free.
// EPI: 0 plain, 1 +bias, 2 +bias+gelu, 3 QKV scatter
// ---------------------------------------------------------------------------
#define GST 10240                 // stage stride in b32 (4 * 128*20)
#define GMM_SMEM (2 * GST * 4)    // bytes = 81920

template <int EPI>
__global__ void __launch_bounds__(256) gemm_mma(
    const float* __restrict__ A, const float* __restrict__ Bt,
    const float* __restrict__ bias, float* __restrict__ C,
    float* __restrict__ Qo, float* __restrict__ Ko, float* __restrict__ Vo,
    int M, int N, int K)
{
    extern __shared__ uint32_t sm[];

    const int tid  = threadIdx.x;
    const int wid  = tid >> 5;
    const int lane = tid & 31;
    const int g    = lane >> 2;          // group id (0..7)
    const int cq   = lane & 3;           // thread-in-group (0..3)
    const int wm   = (wid & 1) * 64;     // warp m offset in CTA tile
    const int wn   = (wid >> 1) * 32;    // warp n offset
    const int m0   = blockIdx.y * 128;
    const int n0   = blockIdx.x * 128;

    // producer mapping: col4 = tid&7 (float4 within row), rows rb+32i
    const int col4 = tid & 7;
    const int rb   = tid >> 3;

    const float* Ap = A  + (size_t)(m0 + rb) * K + col4 * 4;
    const float* Bp = Bt + (size_t)(n0 + rb) * K + col4 * 4;

    float acc[4][4][4];
#pragma unroll
    for (int mt = 0; mt < 4; mt++)
#pragma unroll
        for (int nt = 0; nt < 4; nt++)
#pragma unroll
            for (int e = 0; e < 4; e++) acc[mt][nt][e] = 0.0f;

    const int NC = K >> 5;

    float4 pa[4], pb[4];
#pragma unroll
    for (int i = 0; i < 4; i++) {
        pa[i] = *(const float4*)(Ap + (size_t)(32 * i) * K);
        pb[i] = *(const float4*)(Bp + (size_t)(32 * i) * K);
    }

    for (int c = 0; c < NC; c++) {
        const int p = c & 1;
        uint32_t* sp = sm + p * GST;

        // ---- store prefetched chunk into stage p (bf16 hi/lo split) ----
#pragma unroll
        for (int i = 0; i < 4; i++) {
            int di = (rb + 32 * i) * 20 + col4 * 2;
            uint32_t h0, l0, h1, l1;
            split2(pa[i].x, pa[i].y, h0, l0);
            split2(pa[i].z, pa[i].w, h1, l1);
            *reinterpret_cast<uint2*>(sp + di)        = make_uint2(h0, h1);
            *reinterpret_cast<uint2*>(sp + 2560 + di) = make_uint2(l0, l1);
            split2(pb[i].x, pb[i].y, h0, l0);
            split2(pb[i].z, pb[i].w, h1, l1);
            *reinterpret_cast<uint2*>(sp + 5120 + di) = make_uint2(h0, h1);
            *reinterpret_cast<uint2*>(sp + 7680 + di) = make_uint2(l0, l1);
        }
        __syncthreads();

        // ---- prefetch next chunk ----
        if (c + 1 < NC) {
            const float* Apn = Ap + (c + 1) * 32;
            const float* Bpn = Bp + (c + 1) * 32;
#pragma unroll
            for (int i = 0; i < 4; i++) {
                pa[i] = *(const float4*)(Apn + (size_t)(32 * i) * K);
                pb[i] = *(const float4*)(Bpn + (size_t)(32 * i) * K);
            }
        }

        // ---- compute on stage p: 2 k-slices of 16 ----
#pragma unroll
        for (int ks = 0; ks < 2; ks++) {
            const int kb = ks * 8;
            uint32_t bh[4][2], bl[4][2];
#pragma unroll
            for (int nt = 0; nt < 4; nt++) {
                int bi = 5120 + (wn + nt * 8 + g) * 20 + kb + cq;
                bh[nt][0] = sp[bi];
                bh[nt][1] = sp[bi + 4];
                bl[nt][0] = sp[bi + 2560];
                bl[nt][1] = sp[bi + 2560 + 4];
            }
#pragma unroll
            for (int mt = 0; mt < 4; mt++) {
                int ai = (wm + mt * 16 + g) * 20 + kb + cq;
                uint32_t ah[4], al[4];
                ah[0] = sp[ai];             ah[1] = sp[ai + 160];
                ah[2] = sp[ai + 4];         ah[3] = sp[ai + 160 + 4];
                al[0] = sp[ai + 2560];      al[1] = sp[ai + 2560 + 160];
                al[2] = sp[ai + 2560 + 4];  al[3] = sp[ai + 2560 + 160 + 4];
                // scheme loop outside nt -> acc reuse distance 4
#pragma unroll
                for (int nt = 0; nt < 4; nt++) mma_bf16(acc[mt][nt], ah, bh[nt]);
#pragma unroll
                for (int nt = 0; nt < 4; nt++) mma_bf16(acc[mt][nt], al, bh[nt]);
#pragma unroll
                for (int nt = 0; nt < 4; nt++) mma_bf16(acc[mt][nt], ah, bl[nt]);
            }
        }
        // no trailing sync needed: stage p is only rewritten after the next
        // iteration's barrier.
    }

    // ---- epilogue ----
#pragma unroll
    for (int mt = 0; mt < 4; mt++) {
#pragma unroll
        for (int nt = 0; nt < 4; nt++) {
            int col = n0 + wn + nt * 8 + 2 * cq;
            int r0  = m0 + wm + mt * 16 + g;
            float2 v0 = make_float2(acc[mt][nt][0], acc[mt][nt][1]);
            float2 v1 = make_float2(acc[mt][nt][2], acc[mt][nt][3]);
            if (EPI == 3) {
                int kv = col >> 9, h = (col >> 6) & 7, d = col & 63;
                float* dst = (kv == 0) ? Qo : (kv == 1) ? Ko : Vo;
                int b0i = r0 >> 11, t0i = r0 & (SEQ - 1);
                *(float2*)(dst + (((size_t)b0i * NHEADS + h) * SEQ + t0i) * DHEAD + d) = v0;
                int r1 = r0 + 8;
                int b1i = r1 >> 11, t1i = r1 & (SEQ - 1);
                *(float2*)(dst + (((size_t)b1i * NHEADS + h) * SEQ + t1i) * DHEAD + d) = v1;
            } else {
                if (EPI >= 1) {
                    float2 bb = *(const float2*)(bias + col);
                    v0.x += bb.x; v0.y += bb.y;
                    v1.x += bb.x; v1.y += bb.y;
                }
                if (EPI == 2) {
                    v0.x = gelu_exact(v0.x); v0.y = gelu_exact(v0.y);
                    v1.x = gelu_exact(v1.x); v1.y = gelu_exact(v1.y);
                }
                *(float2*)(C + (size_t)r0 * N + col)       = v0;
                *(float2*)(C + (size_t)(r0 + 8) * N + col) = v1;
            }
        }
    }
}

// ---------------------------------------------------------------------------
// Flash attention (fp32; round-1 proven)
// ---------------------------------------------------------------------------
#define FLASH_LD 68
#define FLASH_SMEM (4 * 64 * FLASH_LD * 4)

__global__ void __launch_bounds__(256) flash_k(
    const float* __restrict__ Q, const float* __restrict__ Kg,
    const float* __restrict__ V, float* __restrict__ O)
{
    extern __shared__ float smf[];
    float* Qs = smf;
    float* Ks = smf + 64 * FLASH_LD;
    float* Vs = smf + 2 * 64 * FLASH_LD;
    float* Ps = smf + 3 * 64 * FLASH_LD;

    const int tid = threadIdx.x;
    const int qt  = blockIdx.x;
    const int h   = blockIdx.y;
    const int b   = blockIdx.z;
    const int t0  = qt * 64;
    const size_t bh = ((size_t)b * NHEADS + h) * SEQ;

    const float* qbase = Q + (bh + t0) * DHEAD;
    for (int e = tid; e < 1024; e += 256) {
        int i  = e >> 4;
        int d4 = (e & 15) << 2;
        float4 qv = *(const float4*)(qbase + i * DHEAD + d4);
        Qs[(d4 + 0) * FLASH_LD + i] = qv.x;
        Qs[(d4 + 1) * FLASH_LD + i] = qv.y;
        Qs[(d4 + 2) * FLASH_LD + i] = qv.z;
        Qs[(d4 + 3) * FLASH_LD + i] = qv.w;
    }

    const int tr = tid >> 4;
    const int tc = tid & 15;

    float o[4][4];
    float mrow[4], lrow[4];
#pragma unroll
    for (int r = 0; r < 4; r++) {
        mrow[r] = -1e30f; lrow[r] = 0.0f;
#pragma unroll
        for (int c = 0; c < 4; c++) o[r][c] = 0.0f;
    }

    for (int j0 = 0; j0 < SEQ; j0 += 64) {
        __syncthreads();
        const float* kbase = Kg + (bh + j0) * DHEAD;
        const float* vbase = V  + (bh + j0) * DHEAD;
        for (int e = tid; e < 1024; e += 256) {
            int j  = e >> 4;
            int d4 = (e & 15) << 2;
            float4 kv = *(const float4*)(kbase + j * DHEAD + d4);
            Ks[(d4 + 0) * FLASH_LD + j] = kv.x;
            Ks[(d4 + 1) * FLASH_LD + j] = kv.y;
            Ks[(d4 + 2) * FLASH_LD + j] = kv.z;
            Ks[(d4 + 3) * FLASH_LD + j] = kv.w;
            float4 vv = *(const float4*)(vbase + j * DHEAD + d4);
            *(float4*)(Vs + j * FLASH_LD + d4) = vv;
        }
        __syncthreads();

        float s[4][4] = {};
#pragma unroll 8
        for (int kk = 0; kk < 64; kk++) {
            float4 q4 = *(const float4*)(Qs + kk * FLASH_LD + tr * 4);
            float4 k4 = *(const float4*)(Ks + kk * FLASH_LD + tc * 4);
            float qa[4] = {q4.x, q4.y, q4.z, q4.w};
            float ka[4] = {k4.x, k4.y, k4.z, k4.w};
#pragma unroll
            for (int r = 0; r < 4; r++)
#pragma unroll
                for (int c = 0; c < 4; c++)
                    s[r][c] = fmaf(qa[r], ka[c], s[r][c]);
        }

#pragma unroll
        for (int r = 0; r < 4; r++) {
            float rm = -1e30f;
#pragma unroll
            for (int c = 0; c < 4; c++) { s[r][c] *= 0.125f; rm = fmaxf(rm, s[r][c]); }
            rm = fmaxf(rm, __shfl_xor_sync(0xffffffffu, rm, 1));
            rm = fmaxf(rm, __shfl_xor_sync(0xffffffffu, rm, 2));
            rm = fmaxf(rm, __shfl_xor_sync(0xffffffffu, rm, 4));
            rm = fmaxf(rm, __shfl_xor_sync(0xffffffffu, rm, 8));
            float mnew = fmaxf(mrow[r], rm);
            float corr = __expf(mrow[r] - mnew);
            mrow[r] = mnew;
            float rs = 0.0f;
#pragma unroll
            for (int c = 0; c < 4; c++) {
                float pv = __expf(s[r][c] - mnew);
                s[r][c] = pv;
                rs += pv;
            }
            rs += __shfl_xor_sync(0xffffffffu, rs, 1);
            rs += __shfl_xor_sync(0xffffffffu, rs, 2);
            rs += __shfl_xor_sync(0xffffffffu, rs, 4);
            rs += __shfl_xor_sync(0xffffffffu, rs, 8);
            lrow[r] = lrow[r] * corr + rs;
#pragma unroll
            for (int c = 0; c < 4; c++) o[r][c] *= corr;
        }

#pragma unroll
        for (int c = 0; c < 4; c++) {
            float4 pv = make_float4(s[0][c], s[1][c], s[2][c], s[3][c]);
            *(float4*)(Ps + (tc * 4 + c) * FLASH_LD + tr * 4) = pv;
        }
        __syncthreads();

#pragma unroll 8
        for (int jj = 0; jj < 64; jj++) {
            float4 p4 = *(const float4*)(Ps + jj * FLASH_LD + tr * 4);
            float4 v4 = *(const float4*)(Vs + jj * FLASH_LD + tc * 4);
            float pa4[4] = {p4.x, p4.y, p4.z, p4.w};
            float va4[4] = {v4.x, v4.y, v4.z, v4.w};
#pragma unroll
            for (int r = 0; r < 4; r++)
#pragma unroll
                for (int c = 0; c < 4; c++)
                    o[r][c] = fmaf(pa4[r], va4[c], o[r][c]);
        }
    }

#pragma unroll
    for (int r = 0; r < 4; r++) {
        float inv = 1.0f / lrow[r];
        float4 ov = make_float4(o[r][0]*inv, o[r][1]*inv, o[r][2]*inv, o[r][3]*inv);
        *(float4*)(O + ((size_t)b * SEQ + t0 + tr * 4 + r) * DMODEL + h * DHEAD + tc * 4) = ov;
    }
}

// ---------------------------------------------------------------------------
// out = LayerNorm(a + resid) * g + bias
// ---------------------------------------------------------------------------
__global__ void __launch_bounds__(128) add_ln_k(
    const float* __restrict__ A, const float* __restrict__ R,
    const float* __restrict__ g, const float* __restrict__ bb,
    float* __restrict__ out)
{
    __shared__ float red[4];
    int row = blockIdx.x;
    int tid = threadIdx.x;
    int warp = tid >> 5, lane = tid & 31;

    float4 a4 = *(const float4*)(A + (size_t)row * DMODEL + tid * 4);
    float4 r4 = *(const float4*)(R + (size_t)row * DMODEL + tid * 4);
    float x0 = a4.x + r4.x, x1 = a4.y + r4.y, x2 = a4.z + r4.z, x3 = a4.w + r4.w;

    float s = x0 + x1 + x2 + x3;
    s += __shfl_xor_sync(0xffffffffu, s, 16);
    s += __shfl_xor_sync(0xffffffffu, s, 8);
    s += __shfl_xor_sync(0xffffffffu, s, 4);
    s += __shfl_xor_sync(0xffffffffu, s, 2);
    s += __shfl_xor_sync(0xffffffffu, s, 1);
    if (lane == 0) red[warp] = s;
    __syncthreads();
    float mu = (red[0] + red[1] + red[2] + red[3]) * (1.0f / DMODEL);
    __syncthreads();

    float d0 = x0 - mu, d1 = x1 - mu, d2 = x2 - mu, d3 = x3 - mu;
    float s2 = d0*d0 + d1*d1 + d2*d2 + d3*d3;
    s2 += __shfl_xor_sync(0xffffffffu, s2, 16);
    s2 += __shfl_xor_sync(0xffffffffu, s2, 8);
    s2 += __shfl_xor_sync(0xffffffffu, s2, 4);
    s2 += __shfl_xor_sync(0xffffffffu, s2, 2);
    s2 += __shfl_xor_sync(0xffffffffu, s2, 1);
    if (lane == 0) red[warp] = s2;
    __syncthreads();
    float var = (red[0] + red[1] + red[2] + red[3]) * (1.0f / DMODEL);
    float rstd = rsqrtf(var + 1e-5f);

    float4 gv = *(const float4*)(g  + tid * 4);
    float4 bv = *(const float4*)(bb + tid * 4);
    float4 ov = make_float4(d0 * rstd * gv.x + bv.x,
                            d1 * rstd * gv.y + bv.y,
                            d2 * rstd * gv.z + bv.z,
                            d3 * rstd * gv.w + bv.w);
    *(float4*)(out + (size_t)row * DMODEL + tid * 4) = ov;
}

// ---------------------------------------------------------------------------
// Head: out[row] = dot(h[row,:], Whead[:,0]) + bhead
// ---------------------------------------------------------------------------
__global__ void head_k(const float* __restrict__ H, const float* __restrict__ W,
                       const float* __restrict__ bh, float* __restrict__ out)
{
    int gw   = (blockIdx.x * blockDim.x + threadIdx.x) >> 5;
    int lane = threadIdx.x & 31;
    const float* r = H + (size_t)gw * DMODEL;
    float s = 0.0f;
#pragma unroll
    for (int k = 0; k < DMODEL / 32; k++)
        s = fmaf(r[lane + k * 32], W[lane + k * 32], s);
    s += __shfl_xor_sync(0xffffffffu, s, 16);
    s += __shfl_xor_sync(0xffffffffu, s, 8);
    s += __shfl_xor_sync(0xffffffffu, s, 4);
    s += __shfl_xor_sync(0xffffffffu, s, 2);
    s += __shfl_xor_sync(0xffffffffu, s, 1);
    if (lane == 0) out[gw] = s + bh[0];
}

// ---------------------------------------------------------------------------
// Launcher
// ---------------------------------------------------------------------------
extern "C" void kernel_launch(void* const* d_in, const int* in_sizes, int n_in,
                              void* d_out, int out_size)
{
    const int*   x     = (const int*)  d_in[0];
    const float* embed = (const float*)d_in[1];
    const float* pe    = (const float*)d_in[2];
    const float* Wqkv  = (const float*)d_in[3];
    const float* W0    = (const float*)d_in[4];
    const float* g1    = (const float*)d_in[5];
    const float* b1    = (const float*)d_in[6];
    const float* g2    = (const float*)d_in[7];
    const float* b2    = (const float*)d_in[8];
    const float* Wl1   = (const float*)d_in[9];
    const float* bl1   = (const float*)d_in[10];
    const float* Wl2   = (const float*)d_in[11];
    const float* bl2   = (const float*)d_in[12];
    const float* Wh    = (const float*)d_in[13];
    const float* bh    = (const float*)d_in[14];
    float* out = (float*)d_out;

    float *hb, *yb, *ab, *aob, *qb, *kb, *vb, *midb;
    float *wtqkv, *wt0, *wt1, *wt2;
    cudaGetSymbolAddress((void**)&hb,    g_h);
    cudaGetSymbolAddress((void**)&yb,    g_y);
    cudaGetSymbolAddress((void**)&ab,    g_a);
    cudaGetSymbolAddress((void**)&aob,   g_ao);
    cudaGetSymbolAddress((void**)&qb,    g_q);
    cudaGetSymbolAddress((void**)&kb,    g_k);
    cudaGetSymbolAddress((void**)&vb,    g_v);
    cudaGetSymbolAddress((void**)&midb,  g_mid);
    cudaGetSymbolAddress((void**)&wtqkv, g_wt_qkv);
    cudaGetSymbolAddress((void**)&wt0,   g_wt_w0);
    cudaGetSymbolAddress((void**)&wt1,   g_wt_l1);
    cudaGetSymbolAddress((void**)&wt2,   g_wt_l2);

    cudaFuncSetAttribute(flash_k, cudaFuncAttributeMaxDynamicSharedMemorySize,
                         FLASH_SMEM);
    cudaFuncSetAttribute(gemm_mma<0>, cudaFuncAttributeMaxDynamicSharedMemorySize, GMM_SMEM);
    cudaFuncSetAttribute(gemm_mma<1>, cudaFuncAttributeMaxDynamicSharedMemorySize, GMM_SMEM);
    cudaFuncSetAttribute(gemm_mma<2>, cudaFuncAttributeMaxDynamicSharedMemorySize, GMM_SMEM);
    cudaFuncSetAttribute(gemm_mma<3>, cudaFuncAttributeMaxDynamicSharedMemorySize, GMM_SMEM);

    // Weight transposes (tiny; once per launch)
    wqkvtrans_k<<<dim3((1536 * 512) / 256, NBLOCKS), 256>>>(Wqkv, wtqkv);
    wtrans_k<<<dim3(16, 16, NBLOCKS), dim3(32, 8)>>>(W0,  wt0, DMODEL, DMODEL);
    wtrans_k<<<dim3(64, 16, NBLOCKS), dim3(32, 8)>>>(Wl1, wt1, DMODEL, DFF);
    wtrans_k<<<dim3(16, 64, NBLOCKS), dim3(32, 8)>>>(Wl2, wt2, DFF, DMODEL);

    embed_k<<<(NROWS * (DMODEL / 4)) / 256, 256>>>(x, embed, pe, hb);

    for (int i = 0; i < NBLOCKS; i++) {
        gemm_mma<3><<<dim3(12, 64), 256, GMM_SMEM>>>(
            hb, wtqkv + (size_t)i * 1536 * 512, nullptr, nullptr,
            qb, kb, vb, NROWS, 3 * DMODEL, DMODEL);

        flash_k<<<dim3(SEQ / 64, NHEADS, BATCH), 256, FLASH_SMEM>>>(qb, kb, vb, aob);

        gemm_mma<0><<<dim3(4, 64), 256, GMM_SMEM>>>(
            aob, wt0 + (size_t)i * DMODEL * DMODEL, nullptr, ab,
            nullptr, nullptr, nullptr, NROWS, DMODEL, DMODEL);

        add_ln_k<<<NROWS, 128>>>(ab, hb, g1 + i * DMODEL, b1 + i * DMODEL, yb);

        gemm_mma<2><<<dim3(16, 64), 256, GMM_SMEM>>>(
            yb, wt1 + (size_t)i * DFF * DMODEL, bl1 + i * DFF, midb,
            nullptr, nullptr, nullptr, NROWS, DFF, DMODEL);

        gemm_mma<1><<<dim3(4, 64), 256, GMM_SMEM>>>(
            midb, wt2 + (size_t)i * DMODEL * DFF, bl2 + i * DMODEL, ab,
            nullptr, nullptr, nullptr, NROWS, DMODEL, DFF);

        add_ln_k<<<NROWS, 128>>>(ab, yb, g2 + i * DMODEL, b2 + i * DMODEL, hb);
    }

    head_k<<<NROWS / 8, 256>>>(hb, Wh, bh, out);
}

// round 5
// speedup vs baseline: 2.6425x; 1.7636x over previous
#include <cuda_runtime.h>
#include <cuda_bf16.h>
#include <cstdint>
#include <math.h>

// Problem constants
#define BATCH  4
#define SEQ    2048
#define DMODEL 512
#define NHEADS 8
#define DHEAD  64
#define DFF    2048
#define NBLOCKS 6
#define NROWS  (BATCH * SEQ)   // 8192

// ---------------------------------------------------------------------------
// Scratch (device globals: allocation-free rule)
// ---------------------------------------------------------------------------
__device__ float g_h  [NROWS * DMODEL];
__device__ float g_y  [NROWS * DMODEL];
__device__ float g_a  [NROWS * DMODEL];
__device__ float g_ao [NROWS * DMODEL];
__device__ float g_q  [BATCH * NHEADS * SEQ * DHEAD];
__device__ float g_k  [BATCH * NHEADS * SEQ * DHEAD];
__device__ float g_v  [BATCH * NHEADS * DHEAD * SEQ];   // transposed [B,H,D,T]
__device__ float g_mid[NROWS * DFF];
// Transposed weights, [N][K] K-major
__device__ float g_wt_qkv[NBLOCKS * 3 * DMODEL * DMODEL];
__device__ float g_wt_w0 [NBLOCKS * DMODEL * DMODEL];
__device__ float g_wt_l1 [NBLOCKS * DFF * DMODEL];
__device__ float g_wt_l2 [NBLOCKS * DMODEL * DFF];

__device__ __forceinline__ float gelu_exact(float x) {
    return 0.5f * x * (1.0f + erff(x * 0.70710678118654752f));
}

// ---------------------------------------------------------------------------
// bf16 split: x = hi + lo
// ---------------------------------------------------------------------------
__device__ __forceinline__ void split2(float x, float y, uint32_t& hi, uint32_t& lo) {
    __nv_bfloat16 hx = __float2bfloat16_rn(x);
    __nv_bfloat16 hy = __float2bfloat16_rn(y);
    float rx = x - __bfloat162float(hx);
    float ry = y - __bfloat162float(hy);
    __nv_bfloat162 H; H.x = hx; H.y = hy;
    __nv_bfloat162 L = __floats2bfloat162_rn(rx, ry);
    hi = *reinterpret_cast<uint32_t*>(&H);
    lo = *reinterpret_cast<uint32_t*>(&L);
}

__device__ __forceinline__ void mma_bf16(float* c, const uint32_t* a, const uint32_t* b) {
    asm volatile(
        "mma.sync.aligned.m16n8k16.row.col.f32.bf16.bf16.f32 "
        "{%0,%1,%2,%3}, {%4,%5,%6,%7}, {%8,%9}, {%0,%1,%2,%3};"
        : "+f"(c[0]), "+f"(c[1]), "+f"(c[2]), "+f"(c[3])
        : "r"(a[0]), "r"(a[1]), "r"(a[2]), "r"(a[3]), "r"(b[0]), "r"(b[1]));
}

// ---------------------------------------------------------------------------
// Embedding + sinusoidal PE
// ---------------------------------------------------------------------------
__global__ void embed_k(const int* __restrict__ x, const float* __restrict__ E,
                        const float* __restrict__ pe, float* __restrict__ H) {
    int idx = blockIdx.x * blockDim.x + threadIdx.x;
    int row = idx >> 7;
    int c   = (idx & 127) << 2;
    int t   = row & (SEQ - 1);
    int tok = x[row];
    float4 e = *(const float4*)(E  + (size_t)tok * DMODEL + c);
    float4 p = *(const float4*)(pe + (size_t)t   * DMODEL + c);
    *(float4*)(H + (size_t)row * DMODEL + c) =
        make_float4(e.x + p.x, e.y + p.y, e.z + p.z, e.w + p.w);
}

// ---------------------------------------------------------------------------
// Weight transposes
// ---------------------------------------------------------------------------
__global__ void wtrans_k(const float* __restrict__ W, float* __restrict__ Wt,
                         int K, int N) {
    __shared__ float t[32][33];
    int n0 = blockIdx.x * 32, k0 = blockIdx.y * 32;
    const float* Wz = W  + (size_t)blockIdx.z * K * N;
    float*      Wtz = Wt + (size_t)blockIdx.z * K * N;
    int tx = threadIdx.x, ty = threadIdx.y;
#pragma unroll
    for (int i = 0; i < 32; i += 8)
        t[ty + i][tx] = Wz[(size_t)(k0 + ty + i) * N + n0 + tx];
    __syncthreads();
#pragma unroll
    for (int i = 0; i < 32; i += 8)
        Wtz[(size_t)(n0 + ty + i) * K + k0 + tx] = t[tx][ty + i];
}

__global__ void wqkvtrans_k(const float* __restrict__ W, float* __restrict__ Wt) {
    int z   = blockIdx.y;
    int idx = blockIdx.x * 256 + threadIdx.x;
    int k   = idx & 511;
    int np  = idx >> 9;
    int kv  = np >> 9, h = (np >> 6) & 7, d = np & 63;
    int n   = d * 24 + kv * 8 + h;
    Wt[(size_t)z * 1536 * 512 + idx] = W[((size_t)z * 512 + k) * 1536 + n];
}

// ---------------------------------------------------------------------------
// bf16x3 warp-MMA GEMM (round-3 proven)
// EPI: 0 plain, 1 +bias, 2 +bias+gelu, 3 QKV scatter (V transposed)
// ---------------------------------------------------------------------------
#define GST 10240
#define GMM_SMEM (2 * GST * 4)

template <int EPI>
__global__ void __launch_bounds__(256) gemm_mma(
    const float* __restrict__ A, const float* __restrict__ Bt,
    const float* __restrict__ bias, float* __restrict__ C,
    float* __restrict__ Qo, float* __restrict__ Ko, float* __restrict__ Vo,
    int M, int N, int K)
{
    extern __shared__ uint32_t sm[];

    const int tid  = threadIdx.x;
    const int wid  = tid >> 5;
    const int lane = tid & 31;
    const int g    = lane >> 2;
    const int cq   = lane & 3;
    const int wm   = (wid & 1) * 64;
    const int wn   = (wid >> 1) * 32;
    const int m0   = blockIdx.y * 128;
    const int n0   = blockIdx.x * 128;

    const int col4 = tid & 7;
    const int rb   = tid >> 3;

    const float* Ap = A  + (size_t)(m0 + rb) * K + col4 * 4;
    const float* Bp = Bt + (size_t)(n0 + rb) * K + col4 * 4;

    float acc[4][4][4];
#pragma unroll
    for (int mt = 0; mt < 4; mt++)
#pragma unroll
        for (int nt = 0; nt < 4; nt++)
#pragma unroll
            for (int e = 0; e < 4; e++) acc[mt][nt][e] = 0.0f;

    const int NC = K >> 5;

    float4 pa[4], pb[4];
#pragma unroll
    for (int i = 0; i < 4; i++) {
        pa[i] = *(const float4*)(Ap + (size_t)(32 * i) * K);
        pb[i] = *(const float4*)(Bp + (size_t)(32 * i) * K);
    }

    for (int c = 0; c < NC; c++) {
        const int p = c & 1;
        uint32_t* sp = sm + p * GST;

#pragma unroll
        for (int i = 0; i < 4; i++) {
            int di = (rb + 32 * i) * 20 + col4 * 2;
            uint32_t h0, l0, h1, l1;
            split2(pa[i].x, pa[i].y, h0, l0);
            split2(pa[i].z, pa[i].w, h1, l1);
            *reinterpret_cast<uint2*>(sp + di)        = make_uint2(h0, h1);
            *reinterpret_cast<uint2*>(sp + 2560 + di) = make_uint2(l0, l1);
            split2(pb[i].x, pb[i].y, h0, l0);
            split2(pb[i].z, pb[i].w, h1, l1);
            *reinterpret_cast<uint2*>(sp + 5120 + di) = make_uint2(h0, h1);
            *reinterpret_cast<uint2*>(sp + 7680 + di) = make_uint2(l0, l1);
        }
        __syncthreads();

        if (c + 1 < NC) {
            const float* Apn = Ap + (c + 1) * 32;
            const float* Bpn = Bp + (c + 1) * 32;
#pragma unroll
            for (int i = 0; i < 4; i++) {
                pa[i] = *(const float4*)(Apn + (size_t)(32 * i) * K);
                pb[i] = *(const float4*)(Bpn + (size_t)(32 * i) * K);
            }
        }

#pragma unroll
        for (int ks = 0; ks < 2; ks++) {
            const int kb = ks * 8;
            uint32_t bh[4][2], bl[4][2];
#pragma unroll
            for (int nt = 0; nt < 4; nt++) {
                int bi = 5120 + (wn + nt * 8 + g) * 20 + kb + cq;
                bh[nt][0] = sp[bi];
                bh[nt][1] = sp[bi + 4];
                bl[nt][0] = sp[bi + 2560];
                bl[nt][1] = sp[bi + 2560 + 4];
            }
#pragma unroll
            for (int mt = 0; mt < 4; mt++) {
                int ai = (wm + mt * 16 + g) * 20 + kb + cq;
                uint32_t ah[4], al[4];
                ah[0] = sp[ai];             ah[1] = sp[ai + 160];
                ah[2] = sp[ai + 4];         ah[3] = sp[ai + 160 + 4];
                al[0] = sp[ai + 2560];      al[1] = sp[ai + 2560 + 160];
                al[2] = sp[ai + 2560 + 4];  al[3] = sp[ai + 2560 + 160 + 4];
#pragma unroll
                for (int nt = 0; nt < 4; nt++) mma_bf16(acc[mt][nt], ah, bh[nt]);
#pragma unroll
                for (int nt = 0; nt < 4; nt++) mma_bf16(acc[mt][nt], al, bh[nt]);
#pragma unroll
                for (int nt = 0; nt < 4; nt++) mma_bf16(acc[mt][nt], ah, bl[nt]);
            }
        }
    }

#pragma unroll
    for (int mt = 0; mt < 4; mt++) {
#pragma unroll
        for (int nt = 0; nt < 4; nt++) {
            int col = n0 + wn + nt * 8 + 2 * cq;
            int r0  = m0 + wm + mt * 16 + g;
            float2 v0 = make_float2(acc[mt][nt][0], acc[mt][nt][1]);
            float2 v1 = make_float2(acc[mt][nt][2], acc[mt][nt][3]);
            if (EPI == 3) {
                int kv = col >> 9, h = (col >> 6) & 7, d = col & 63;
                int b0i = r0 >> 11, t0i = r0 & (SEQ - 1);
                int r1 = r0 + 8;
                int b1i = r1 >> 11, t1i = r1 & (SEQ - 1);
                if (kv == 2) {
                    // V transposed: [B,H,D,T]
                    size_t base0 = (((size_t)b0i * NHEADS + h) * DHEAD + d) * SEQ;
                    size_t base1 = (((size_t)b1i * NHEADS + h) * DHEAD + d) * SEQ;
                    Vo[base0 + t0i]       = v0.x;
                    Vo[base0 + SEQ + t0i] = v0.y;
                    Vo[base1 + t1i]       = v1.x;
                    Vo[base1 + SEQ + t1i] = v1.y;
                } else {
                    float* dst = (kv == 0) ? Qo : Ko;
                    *(float2*)(dst + (((size_t)b0i * NHEADS + h) * SEQ + t0i) * DHEAD + d) = v0;
                    *(float2*)(dst + (((size_t)b1i * NHEADS + h) * SEQ + t1i) * DHEAD + d) = v1;
                }
            } else {
                if (EPI >= 1) {
                    float2 bb = *(const float2*)(bias + col);
                    v0.x += bb.x; v0.y += bb.y;
                    v1.x += bb.x; v1.y += bb.y;
                }
                if (EPI == 2) {
                    v0.x = gelu_exact(v0.x); v0.y = gelu_exact(v0.y);
                    v1.x = gelu_exact(v1.x); v1.y = gelu_exact(v1.y);
                }
                *(float2*)(C + (size_t)r0 * N + col)       = v0;
                *(float2*)(C + (size_t)(r0 + 8) * N + col) = v1;
            }
        }
    }
}

// ---------------------------------------------------------------------------
// Flash attention, bf16x3 mma.sync.  CTA = 128 queries x 64-key blocks,
// 8 warps, warp w owns rows [16w,16w+16).  Q/K/V hi+lo in smem, row stride
// 36 b32 (conflict-free fragment LDS).  P stays in registers (S-frag == A-frag).
// V is consumed from transposed layout [B,H,D,T].
// ---------------------------------------------------------------------------
#define FSC 36
#define FQH 0
#define FQL 4608
#define FKH 9216
#define FKL 11520
#define FVH 13824
#define FVL 16128
#define FLASH2_SMEM (18432 * 4)

__global__ void __launch_bounds__(256, 2) flash_mma(
    const float* __restrict__ Q, const float* __restrict__ Kg,
    const float* __restrict__ Vt, float* __restrict__ O)
{
    extern __shared__ uint32_t sm[];
    const int tid  = threadIdx.x;
    const int wid  = tid >> 5;
    const int lane = tid & 31;
    const int g    = lane >> 2;
    const int cq   = lane & 3;
    const int t0   = blockIdx.x * 128;
    const int h    = blockIdx.y;
    const int b    = blockIdx.z;
    const size_t bh = ((size_t)b * NHEADS + h) * SEQ;
    const float SCL = 0.18033688011112042f;   // 0.125 * log2(e)

    // ---- load Q (prescaled, bf16 split) ----
    {
        int row = tid >> 1;
        const float* qp = Q + (bh + t0 + row) * DHEAD;
#pragma unroll
        for (int i = 0; i < 8; i++) {
            int f4 = (tid & 1) + 2 * i;
            float4 v = *(const float4*)(qp + f4 * 4);
            v.x *= SCL; v.y *= SCL; v.z *= SCL; v.w *= SCL;
            uint32_t h0, l0, h1, l1;
            split2(v.x, v.y, h0, l0);
            split2(v.z, v.w, h1, l1);
            int di = row * FSC + f4 * 2;
            sm[FQH + di] = h0; sm[FQH + di + 1] = h1;
            sm[FQL + di] = l0; sm[FQL + di + 1] = l1;
        }
    }

    float o[8][4];
#pragma unroll
    for (int dt = 0; dt < 8; dt++)
#pragma unroll
        for (int e = 0; e < 4; e++) o[dt][e] = 0.0f;
    float m0 = -1e30f, m1 = -1e30f, l0 = 0.0f, l1 = 0.0f;

    const int prow = tid >> 2;                 // 0..63: j-row for K, d-row for V
    const float* vrow = Vt + ((((size_t)b * NHEADS + h) * DHEAD) + prow) * SEQ;
    const int qr = wid * 16 + g;

    for (int jb = 0; jb < SEQ; jb += 64) {
        __syncthreads();    // previous block's consumers done (also orders Q writes)
        // ---- produce K, V tiles ----
        const float* kp = Kg + (bh + jb + prow) * DHEAD;
#pragma unroll
        for (int i = 0; i < 4; i++) {
            int f4 = (tid & 3) + i * 4;
            int di = prow * FSC + f4 * 2;
            float4 v = *(const float4*)(kp + f4 * 4);
            uint32_t h0, lo0, h1, lo1;
            split2(v.x, v.y, h0, lo0);
            split2(v.z, v.w, h1, lo1);
            sm[FKH + di] = h0;  sm[FKH + di + 1] = h1;
            sm[FKL + di] = lo0; sm[FKL + di + 1] = lo1;
            float4 w = *(const float4*)(vrow + jb + f4 * 4);
            split2(w.x, w.y, h0, lo0);
            split2(w.z, w.w, h1, lo1);
            sm[FVH + di] = h0;  sm[FVH + di + 1] = h1;
            sm[FVL + di] = lo0; sm[FVL + di + 1] = lo1;
        }
        __syncthreads();

        // ---- S = Q @ K^T (bf16x3) ----
        float s[8][4];
#pragma unroll
        for (int nt = 0; nt < 8; nt++)
#pragma unroll
            for (int e = 0; e < 4; e++) s[nt][e] = 0.0f;

#pragma unroll
        for (int ks = 0; ks < 4; ks++) {
            uint32_t qh[4], ql[4];
            int qi = qr * FSC + ks * 8 + cq;
            qh[0] = sm[FQH + qi];            qh[1] = sm[FQH + qi + 8 * FSC];
            qh[2] = sm[FQH + qi + 4];        qh[3] = sm[FQH + qi + 8 * FSC + 4];
            ql[0] = sm[FQL + qi];            ql[1] = sm[FQL + qi + 8 * FSC];
            ql[2] = sm[FQL + qi + 4];        ql[3] = sm[FQL + qi + 8 * FSC + 4];
            uint32_t kh[8][2], kl[8][2];
#pragma unroll
            for (int nt = 0; nt < 8; nt++) {
                int ki = (nt * 8 + g) * FSC + ks * 8 + cq;
                kh[nt][0] = sm[FKH + ki]; kh[nt][1] = sm[FKH + ki + 4];
                kl[nt][0] = sm[FKL + ki]; kl[nt][1] = sm[FKL + ki + 4];
            }
#pragma unroll
            for (int nt = 0; nt < 8; nt++) mma_bf16(s[nt], qh, kh[nt]);
#pragma unroll
            for (int nt = 0; nt < 8; nt++) mma_bf16(s[nt], ql, kh[nt]);
#pragma unroll
            for (int nt = 0; nt < 8; nt++) mma_bf16(s[nt], qh, kl[nt]);
        }

        // ---- online softmax (base 2) ----
        float rm0 = -1e30f, rm1 = -1e30f;
#pragma unroll
        for (int nt = 0; nt < 8; nt++) {
            rm0 = fmaxf(rm0, fmaxf(s[nt][0], s[nt][1]));
            rm1 = fmaxf(rm1, fmaxf(s[nt][2], s[nt][3]));
        }
        rm0 = fmaxf(rm0, __shfl_xor_sync(0xffffffffu, rm0, 1));
        rm0 = fmaxf(rm0, __shfl_xor_sync(0xffffffffu, rm0, 2));
        rm1 = fmaxf(rm1, __shfl_xor_sync(0xffffffffu, rm1, 1));
        rm1 = fmaxf(rm1, __shfl_xor_sync(0xffffffffu, rm1, 2));
        float mn0 = fmaxf(m0, rm0), mn1 = fmaxf(m1, rm1);
        float c0 = exp2f(m0 - mn0), c1 = exp2f(m1 - mn1);
        m0 = mn0; m1 = mn1;
        float rs0 = 0.0f, rs1 = 0.0f;
#pragma unroll
        for (int nt = 0; nt < 8; nt++) {
            s[nt][0] = exp2f(s[nt][0] - mn0);
            s[nt][1] = exp2f(s[nt][1] - mn0);
            s[nt][2] = exp2f(s[nt][2] - mn1);
            s[nt][3] = exp2f(s[nt][3] - mn1);
            rs0 += s[nt][0] + s[nt][1];
            rs1 += s[nt][2] + s[nt][3];
        }
        rs0 += __shfl_xor_sync(0xffffffffu, rs0, 1);
        rs0 += __shfl_xor_sync(0xffffffffu, rs0, 2);
        rs1 += __shfl_xor_sync(0xffffffffu, rs1, 1);
        rs1 += __shfl_xor_sync(0xffffffffu, rs1, 2);
        l0 = l0 * c0 + rs0;
        l1 = l1 * c1 + rs1;
#pragma unroll
        for (int dt = 0; dt < 8; dt++) {
            o[dt][0] *= c0; o[dt][1] *= c0;
            o[dt][2] *= c1; o[dt][3] *= c1;
        }

        // ---- P fragments (register-only: S-frag == A-frag) ----
        uint32_t ph[4][4], pl[4][4];
#pragma unroll
        for (int kj = 0; kj < 4; kj++) {
            split2(s[2*kj][0],   s[2*kj][1],   ph[kj][0], pl[kj][0]);
            split2(s[2*kj][2],   s[2*kj][3],   ph[kj][1], pl[kj][1]);
            split2(s[2*kj+1][0], s[2*kj+1][1], ph[kj][2], pl[kj][2]);
            split2(s[2*kj+1][2], s[2*kj+1][3], ph[kj][3], pl[kj][3]);
        }

        // ---- O += P @ V (bf16x3) ----
#pragma unroll
        for (int kj = 0; kj < 4; kj++) {
            uint32_t vh[8][2], vl[8][2];
#pragma unroll
            for (int dt = 0; dt < 8; dt++) {
                int vi = (dt * 8 + g) * FSC + kj * 8 + cq;
                vh[dt][0] = sm[FVH + vi]; vh[dt][1] = sm[FVH + vi + 4];
                vl[dt][0] = sm[FVL + vi]; vl[dt][1] = sm[FVL + vi + 4];
            }
#pragma unroll
            for (int dt = 0; dt < 8; dt++) mma_bf16(o[dt], ph[kj], vh[dt]);
#pragma unroll
            for (int dt = 0; dt < 8; dt++) mma_bf16(o[dt], pl[kj], vh[dt]);
#pragma unroll
            for (int dt = 0; dt < 8; dt++) mma_bf16(o[dt], ph[kj], vl[dt]);
        }
    }

    // ---- write O ----
    float inv0 = 1.0f / l0, inv1 = 1.0f / l1;
    int row0 = t0 + wid * 16 + g;
#pragma unroll
    for (int dt = 0; dt < 8; dt++) {
        int col = h * DHEAD + dt * 8 + 2 * cq;
        *(float2*)(O + ((size_t)b * SEQ + row0) * DMODEL + col) =
            make_float2(o[dt][0] * inv0, o[dt][1] * inv0);
        *(float2*)(O + ((size_t)b * SEQ + row0 + 8) * DMODEL + col) =
            make_float2(o[dt][2] * inv1, o[dt][3] * inv1);
    }
}

// ---------------------------------------------------------------------------
// out = LayerNorm(a + resid) * g + bias
// ---------------------------------------------------------------------------
__global__ void __launch_bounds__(128) add_ln_k(
    const float* __restrict__ A, const float* __restrict__ R,
    const float* __restrict__ g, const float* __restrict__ bb,
    float* __restrict__ out)
{
    __shared__ float red[4];
    int row = blockIdx.x;
    int tid = threadIdx.x;
    int warp = tid >> 5, lane = tid & 31;

    float4 a4 = *(const float4*)(A + (size_t)row * DMODEL + tid * 4);
    float4 r4 = *(const float4*)(R + (size_t)row * DMODEL + tid * 4);
    float x0 = a4.x + r4.x, x1 = a4.y + r4.y, x2 = a4.z + r4.z, x3 = a4.w + r4.w;

    float s = x0 + x1 + x2 + x3;
    s += __shfl_xor_sync(0xffffffffu, s, 16);
    s += __shfl_xor_sync(0xffffffffu, s, 8);
    s += __shfl_xor_sync(0xffffffffu, s, 4);
    s += __shfl_xor_sync(0xffffffffu, s, 2);
    s += __shfl_xor_sync(0xffffffffu, s, 1);
    if (lane == 0) red[warp] = s;
    __syncthreads();
    float mu = (red[0] + red[1] + red[2] + red[3]) * (1.0f / DMODEL);
    __syncthreads();

    float d0 = x0 - mu, d1 = x1 - mu, d2 = x2 - mu, d3 = x3 - mu;
    float s2 = d0*d0 + d1*d1 + d2*d2 + d3*d3;
    s2 += __shfl_xor_sync(0xffffffffu, s2, 16);
    s2 += __shfl_xor_sync(0xffffffffu, s2, 8);
    s2 += __shfl_xor_sync(0xffffffffu, s2, 4);
    s2 += __shfl_xor_sync(0xffffffffu, s2, 2);
    s2 += __shfl_xor_sync(0xffffffffu, s2, 1);
    if (lane == 0) red[warp] = s2;
    __syncthreads();
    float var = (red[0] + red[1] + red[2] + red[3]) * (1.0f / DMODEL);
    float rstd = rsqrtf(var + 1e-5f);

    float4 gv = *(const float4*)(g  + tid * 4);
    float4 bv = *(const float4*)(bb + tid * 4);
    float4 ov = make_float4(d0 * rstd * gv.x + bv.x,
                            d1 * rstd * gv.y + bv.y,
                            d2 * rstd * gv.z + bv.z,
                            d3 * rstd * gv.w + bv.w);
    *(float4*)(out + (size_t)row * DMODEL + tid * 4) = ov;
}

// ---------------------------------------------------------------------------
// Head
// ---------------------------------------------------------------------------
__global__ void head_k(const float* __restrict__ H, const float* __restrict__ W,
                       const float* __restrict__ bh, float* __restrict__ out)
{
    int gw   = (blockIdx.x * blockDim.x + threadIdx.x) >> 5;
    int lane = threadIdx.x & 31;
    const float* r = H + (size_t)gw * DMODEL;
    float s = 0.0f;
#pragma unroll
    for (int k = 0; k < DMODEL / 32; k++)
        s = fmaf(r[lane + k * 32], W[lane + k * 32], s);
    s += __shfl_xor_sync(0xffffffffu, s, 16);
    s += __shfl_xor_sync(0xffffffffu, s, 8);
    s += __shfl_xor_sync(0xffffffffu, s, 4);
    s += __shfl_xor_sync(0xffffffffu, s, 2);
    s += __shfl_xor_sync(0xffffffffu, s, 1);
    if (lane == 0) out[gw] = s + bh[0];
}

// ---------------------------------------------------------------------------
// Launcher
// ---------------------------------------------------------------------------
extern "C" void kernel_launch(void* const* d_in, const int* in_sizes, int n_in,
                              void* d_out, int out_size)
{
    const int*   x     = (const int*)  d_in[0];
    const float* embed = (const float*)d_in[1];
    const float* pe    = (const float*)d_in[2];
    const float* Wqkv  = (const float*)d_in[3];
    const float* W0    = (const float*)d_in[4];
    const float* g1    = (const float*)d_in[5];
    const float* b1    = (const float*)d_in[6];
    const float* g2    = (const float*)d_in[7];
    const float* b2    = (const float*)d_in[8];
    const float* Wl1   = (const float*)d_in[9];
    const float* bl1   = (const float*)d_in[10];
    const float* Wl2   = (const float*)d_in[11];
    const float* bl2   = (const float*)d_in[12];
    const float* Wh    = (const float*)d_in[13];
    const float* bh    = (const float*)d_in[14];
    float* out = (float*)d_out;

    float *hb, *yb, *ab, *aob, *qb, *kb, *vb, *midb;
    float *wtqkv, *wt0, *wt1, *wt2;
    cudaGetSymbolAddress((void**)&hb,    g_h);
    cudaGetSymbolAddress((void**)&yb,    g_y);
    cudaGetSymbolAddress((void**)&ab,    g_a);
    cudaGetSymbolAddress((void**)&aob,   g_ao);
    cudaGetSymbolAddress((void**)&qb,    g_q);
    cudaGetSymbolAddress((void**)&kb,    g_k);
    cudaGetSymbolAddress((void**)&vb,    g_v);
    cudaGetSymbolAddress((void**)&midb,  g_mid);
    cudaGetSymbolAddress((void**)&wtqkv, g_wt_qkv);
    cudaGetSymbolAddress((void**)&wt0,   g_wt_w0);
    cudaGetSymbolAddress((void**)&wt1,   g_wt_l1);
    cudaGetSymbolAddress((void**)&wt2,   g_wt_l2);

    cudaFuncSetAttribute(flash_mma, cudaFuncAttributeMaxDynamicSharedMemorySize,
                         FLASH2_SMEM);
    cudaFuncSetAttribute(gemm_mma<0>, cudaFuncAttributeMaxDynamicSharedMemorySize, GMM_SMEM);
    cudaFuncSetAttribute(gemm_mma<1>, cudaFuncAttributeMaxDynamicSharedMemorySize, GMM_SMEM);
    cudaFuncSetAttribute(gemm_mma<2>, cudaFuncAttributeMaxDynamicSharedMemorySize, GMM_SMEM);
    cudaFuncSetAttribute(gemm_mma<3>, cudaFuncAttributeMaxDynamicSharedMemorySize, GMM_SMEM);

    wqkvtrans_k<<<dim3((1536 * 512) / 256, NBLOCKS), 256>>>(Wqkv, wtqkv);
    wtrans_k<<<dim3(16, 16, NBLOCKS), dim3(32, 8)>>>(W0,  wt0, DMODEL, DMODEL);
    wtrans_k<<<dim3(64, 16, NBLOCKS), dim3(32, 8)>>>(Wl1, wt1, DMODEL, DFF);
    wtrans_k<<<dim3(16, 64, NBLOCKS), dim3(32, 8)>>>(Wl2, wt2, DFF, DMODEL);

    embed_k<<<(NROWS * (DMODEL / 4)) / 256, 256>>>(x, embed, pe, hb);

    for (int i = 0; i < NBLOCKS; i++) {
        gemm_mma<3><<<dim3(12, 64), 256, GMM_SMEM>>>(
            hb, wtqkv + (size_t)i * 1536 * 512, nullptr, nullptr,
            qb, kb, vb, NROWS, 3 * DMODEL, DMODEL);

        flash_mma<<<dim3(SEQ / 128, NHEADS, BATCH), 256, FLASH2_SMEM>>>(qb, kb, vb, aob);

        gemm_mma<0><<<dim3(4, 64), 256, GMM_SMEM>>>(
            aob, wt0 + (size_t)i * DMODEL * DMODEL, nullptr, ab,
            nullptr, nullptr, nullptr, NROWS, DMODEL, DMODEL);

        add_ln_k<<<NROWS, 128>>>(ab, hb, g1 + i * DMODEL, b1 + i * DMODEL, yb);

        gemm_mma<2><<<dim3(16, 64), 256, GMM_SMEM>>>(
            yb, wt1 + (size_t)i * DFF * DMODEL, bl1 + i * DFF, midb,
            nullptr, nullptr, nullptr, NROWS, DFF, DMODEL);

        gemm_mma<1><<<dim3(4, 64), 256, GMM_SMEM>>>(
            midb, wt2 + (size_t)i * DMODEL * DFF, bl2 + i * DMODEL, ab,
            nullptr, nullptr, nullptr, NROWS, DMODEL, DFF);

        add_ln_k<<<NROWS, 128>>>(ab, yb, g2 + i * DMODEL, b2 + i * DMODEL, hb);
    }

    head_k<<<NROWS / 8, 256>>>(hb, Wh, bh, out);
}